// round 3
// baseline (speedup 1.0000x reference)
#include <cuda_runtime.h>
#include <math.h>

#define B_  64
#define T_  2048
#define IN_ 128
#define H_  256
#define M_  (B_ * T_)
#define TROWS 4            // batch rows per cluster
#define RANKS 8            // CTAs per cluster

// ---------------- scratch (static device allocations; no cudaMalloc) ----------------
__device__ float g_xp[(size_t)B_ * T_ * H_];    // xp0 = x @ W_ih0^T + biases
__device__ float g_h2last[(size_t)B_ * H_];     // h2[:, T-1, :]

// ---------------- packed fp32x2 helpers (sm_103a) ----------------
__device__ __forceinline__ void fma2(unsigned long long &d, unsigned long long a, unsigned long long b) {
    asm("fma.rn.f32x2 %0, %1, %2, %0;" : "+l"(d) : "l"(a), "l"(b));
}
__device__ __forceinline__ unsigned long long splat2(float x) {
    unsigned long long r; asm("mov.b64 %0, {%1, %1};" : "=l"(r) : "f"(x)); return r;
}
__device__ __forceinline__ float lo2(unsigned long long v) { return __uint_as_float((unsigned)(v & 0xffffffffULL)); }
__device__ __forceinline__ float hi2(unsigned long long v) { return __uint_as_float((unsigned)(v >> 32)); }

// ---------------- cluster / mbarrier helpers ----------------
__device__ __forceinline__ unsigned su32(const void* p) {
    return (unsigned)__cvta_generic_to_shared(p);
}
__device__ __forceinline__ unsigned cta_rank() {
    unsigned r; asm("mov.u32 %0, %%cluster_ctarank;" : "=r"(r)); return r;
}
__device__ __forceinline__ unsigned mapa_u32(unsigned addr, unsigned rank) {
    unsigned r; asm("mapa.shared::cluster.u32 %0, %1, %2;" : "=r"(r) : "r"(addr), "r"(rank));
    return r;
}
__device__ __forceinline__ void mbar_init(unsigned addr, unsigned cnt) {
    asm volatile("mbarrier.init.shared.b64 [%0], %1;" :: "r"(addr), "r"(cnt) : "memory");
}
__device__ __forceinline__ void mbar_expect_tx(unsigned addr, unsigned bytes) {
    asm volatile("mbarrier.arrive.expect_tx.shared.b64 _, [%0], %1;" :: "r"(addr), "r"(bytes) : "memory");
}
__device__ __forceinline__ void mbar_wait_cluster(unsigned addr, unsigned parity) {
    asm volatile(
        "{\n\t.reg .pred P;\n\t"
        "WL_%=:\n\t"
        "mbarrier.try_wait.parity.acquire.cluster.shared::cta.b64 P, [%0], %1, 0x989680;\n\t"
        "@P bra.uni WD_%=;\n\t"
        "bra.uni WL_%=;\n\t"
        "WD_%=:\n\t}"
        :: "r"(addr), "r"(parity) : "memory");
}
__device__ __forceinline__ void st_async_f32(unsigned remote_addr, float v, unsigned remote_mbar) {
    asm volatile(
        "st.async.shared::cluster.mbarrier::complete_tx::bytes.b32 [%0], %1, [%2];"
        :: "r"(remote_addr), "r"(__float_as_uint(v)), "r"(remote_mbar) : "memory");
}
__device__ __forceinline__ void cluster_sync_() {
    asm volatile("barrier.cluster.arrive.aligned;" ::: "memory");
    asm volatile("barrier.cluster.wait.aligned;" ::: "memory");
}

// =====================================================================================
// Phase A: xp0[m][n] = sum_k x[m][k] * W_ih0[n][k] + b_ih0[n] + b_hh0[n]
// =====================================================================================
__global__ __launch_bounds__(256, 2)
void gemm_bias_kernel(const float* __restrict__ A, const float* __restrict__ W,
                      const float* __restrict__ bias0, const float* __restrict__ bias1,
                      float* __restrict__ C, int K)
{
    __shared__ float a_sm[16][132];
    __shared__ float b_sm[16][132];

    const int tid = threadIdx.x;
    const int tx = tid & 15, ty = tid >> 4;
    const int mBase = blockIdx.x * 128;
    const int nBase = blockIdx.y * 128;

    unsigned long long acc[8][4];
#pragma unroll
    for (int i = 0; i < 8; i++)
#pragma unroll
        for (int j = 0; j < 4; j++) acc[i][j] = 0ULL;

    for (int kt = 0; kt < K; kt += 16) {
#pragma unroll
        for (int l = 0; l < 2; l++) {
            int idx = l * 256 + tid;
            int row = idx >> 2, kq = idx & 3;
            float4 v = *(const float4*)(A + (size_t)(mBase + row) * K + kt + kq * 4);
            a_sm[kq * 4 + 0][row] = v.x; a_sm[kq * 4 + 1][row] = v.y;
            a_sm[kq * 4 + 2][row] = v.z; a_sm[kq * 4 + 3][row] = v.w;
        }
#pragma unroll
        for (int l = 0; l < 2; l++) {
            int idx = l * 256 + tid;
            int row = idx >> 2, kq = idx & 3;
            float4 v = *(const float4*)(W + (size_t)(nBase + row) * K + kt + kq * 4);
            b_sm[kq * 4 + 0][row] = v.x; b_sm[kq * 4 + 1][row] = v.y;
            b_sm[kq * 4 + 2][row] = v.z; b_sm[kq * 4 + 3][row] = v.w;
        }
        __syncthreads();

#pragma unroll
        for (int kk = 0; kk < 16; kk++) {
            float4 a0 = *(const float4*)&a_sm[kk][ty * 8];
            float4 a1 = *(const float4*)&a_sm[kk][ty * 8 + 4];
            ulonglong2 b0 = *(const ulonglong2*)&b_sm[kk][tx * 8];
            ulonglong2 b1 = *(const ulonglong2*)&b_sm[kk][tx * 8 + 4];
            float av[8] = {a0.x, a0.y, a0.z, a0.w, a1.x, a1.y, a1.z, a1.w};
#pragma unroll
            for (int i = 0; i < 8; i++) {
                unsigned long long s = splat2(av[i]);
                fma2(acc[i][0], s, b0.x);
                fma2(acc[i][1], s, b0.y);
                fma2(acc[i][2], s, b1.x);
                fma2(acc[i][3], s, b1.y);
            }
        }
        __syncthreads();
    }

    const int n0 = nBase + tx * 8;
    float bj[8];
#pragma unroll
    for (int j = 0; j < 8; j++) bj[j] = bias0[n0 + j] + bias1[n0 + j];

#pragma unroll
    for (int i = 0; i < 8; i++) {
        int m = mBase + ty * 8 + i;
        float4 o0, o1;
        o0.x = lo2(acc[i][0]) + bj[0]; o0.y = hi2(acc[i][0]) + bj[1];
        o0.z = lo2(acc[i][1]) + bj[2]; o0.w = hi2(acc[i][1]) + bj[3];
        o1.x = lo2(acc[i][2]) + bj[4]; o1.y = hi2(acc[i][2]) + bj[5];
        o1.z = lo2(acc[i][3]) + bj[6]; o1.w = hi2(acc[i][3]) + bj[7];
        *(float4*)(C + (size_t)m * H_ + n0)     = o0;
        *(float4*)(C + (size_t)m * H_ + n0 + 4) = o1;
    }
}

// =====================================================================================
// Fused two-layer recurrence. 16 clusters x 8 CTAs, 4 batch rows per cluster.
// CTA (rank) owns outputs [32*rank, 32*rank+32) of h1 and h2; weight slices of
// W_hh0 / W_ih1 / W_hh1 live in registers (48 packed f32x2 per thread).
// Pipeline: iteration t computes h1[t] (layer 0) and h2[t-1] (layer 1).
// Per step, each CTA broadcasts its h1/h2 chunks to the 7 peers via st.async
// with tx-count mbarriers (double-buffered, one mbar per parity).
// =====================================================================================
__global__ void __cluster_dims__(RANKS, 1, 1) __launch_bounds__(256, 1)
rnn_fused(const float* __restrict__ xp,
          const float* __restrict__ Whh0,
          const float* __restrict__ Wih1, const float* __restrict__ Whh1,
          const float* __restrict__ bih1, const float* __restrict__ bhh1,
          float* __restrict__ h2last)
{
    __shared__ __align__(16) float h1b[2][TROWS][256];
    __shared__ __align__(16) float h2b[2][TROWS][256];
    __shared__ __align__(16) float p_sm[8][264];
    __shared__ __align__(8)  unsigned long long mbar[2];

    const int tid = threadIdx.x;
    const unsigned rank = cta_rank();
    const int cid = blockIdx.x >> 3;            // cluster id 0..15

    // matvec mapping: thread (o, g); k-assignment strided (k = 4g + 32j) for
    // conflict-free broadcast LDS of h
    const int g = tid & 7, o = tid >> 3;
    const int o_glob = (int)rank * 32 + o;

    // epilogue mapping: one thread per output (mat, row, o)
    const int emat = tid >> 7, erow = (tid >> 5) & 3, eo = tid & 31;
    const int eo_glob = (int)rank * 32 + eo;

    // ---- weight slices into registers ----
    unsigned long long wA[16], wB[16], wC[16];
#pragma unroll
    for (int j = 0; j < 8; ++j) {
        ulonglong2 a = *(const ulonglong2*)(Whh0 + (size_t)o_glob * H_ + j * 32 + g * 4);
        wA[2 * j] = a.x; wA[2 * j + 1] = a.y;
        ulonglong2 b = *(const ulonglong2*)(Wih1 + (size_t)o_glob * H_ + j * 32 + g * 4);
        wB[2 * j] = b.x; wB[2 * j + 1] = b.y;
        ulonglong2 c = *(const ulonglong2*)(Whh1 + (size_t)o_glob * H_ + j * 32 + g * 4);
        wC[2 * j] = c.x; wC[2 * j + 1] = c.y;
    }
    const float ebias = bih1[eo_glob] + bhh1[eo_glob];   // layer-1 epilogue bias

    // ---- init ----
    for (int i = tid; i < 2 * TROWS * 256; i += 256) {
        ((float*)h1b)[i] = 0.f; ((float*)h2b)[i] = 0.f;
    }
    if (tid == 0) { mbar_init(su32(&mbar[0]), 1); mbar_init(su32(&mbar[1]), 1); }
    __syncthreads();
    cluster_sync_();

    const unsigned my_anchor = su32(&h1b[0][0][0]);
    const unsigned my_mbar   = su32(&mbar[0]);
    unsigned peer_anchor[7], peer_mbar[7];
#pragma unroll
    for (int i = 0; i < 7; ++i) {
        unsigned p = (rank + 1u + (unsigned)i) & 7u;
        peer_anchor[i] = mapa_u32(my_anchor, p);
        peer_mbar[i]   = mapa_u32(my_mbar, p);
    }

    const size_t xbase = ((size_t)(cid * TROWS + erow) * T_) * H_ + eo_glob;

    for (int t = 0; t <= T_; ++t) {
        const int cb = t & 1, pb = cb ^ 1;

        // prefetch xp for this step's layer-0 epilogue (hidden under wait+matvec)
        float xv = 0.f;
        if (emat == 0 && t < T_) xv = __ldg(xp + xbase + (size_t)t * H_);

        if (t > 0)
            mbar_wait_cluster(my_mbar + (unsigned)pb * 8u, (unsigned)((t - 1) >> 1) & 1u);
        if (t < T_ && tid == 0) {
            unsigned bytes = 3584u + (t >= 1 ? 3584u : 0u);   // h1 chunks (+ h2 chunks)
            mbar_expect_tx(my_mbar + (unsigned)cb * 8u, bytes);
        }

        // ---- matvec: h1[t] partials (wA) and h2[t-1] partials (wB on h1, wC on h2) ----
        unsigned long long aA[TROWS] = {0, 0, 0, 0};
        unsigned long long aL[TROWS] = {0, 0, 0, 0};
#pragma unroll
        for (int r = 0; r < TROWS; ++r) {
            const float* h1p = &h1b[pb][r][g * 4];
            const float* h2p = &h2b[pb][r][g * 4];
#pragma unroll
            for (int j = 0; j < 8; ++j) {
                ulonglong2 v1 = *(const ulonglong2*)(h1p + j * 32);
                fma2(aA[r], v1.x, wA[2 * j]); fma2(aA[r], v1.y, wA[2 * j + 1]);
                fma2(aL[r], v1.x, wB[2 * j]); fma2(aL[r], v1.y, wB[2 * j + 1]);
                ulonglong2 v2 = *(const ulonglong2*)(h2p + j * 32);
                fma2(aL[r], v2.x, wC[2 * j]); fma2(aL[r], v2.y, wC[2 * j + 1]);
            }
        }
#pragma unroll
        for (int r = 0; r < TROWS; ++r) {
            p_sm[g][r * 32 + o]       = lo2(aA[r]) + hi2(aA[r]);
            p_sm[g][128 + r * 32 + o] = lo2(aL[r]) + hi2(aL[r]);
        }
        __syncthreads();

        // ---- epilogue: one output per thread ----
        {
            float s = emat ? ebias : xv;
#pragma unroll
            for (int gg = 0; gg < 8; ++gg) s += p_sm[gg][tid];
            float h = tanhf(s);

            const bool send = emat ? (t >= 1 && t < T_) : (t < T_);
            if (send) {
                float* own = emat ? &h2b[cb][erow][eo_glob] : &h1b[cb][erow][eo_glob];
                *own = h;
                unsigned loff = su32(own) - my_anchor;
#pragma unroll
                for (int p = 0; p < 7; ++p)
                    st_async_f32(peer_anchor[p] + loff, h,
                                 peer_mbar[p] + (unsigned)cb * 8u);
            }
            if (emat == 1 && t == T_)
                h2last[(size_t)(cid * TROWS + erow) * H_ + eo_glob] = h;
        }
        __syncthreads();
    }
    cluster_sync_();
}

// =====================================================================================
// Final FC: out[b] = dot(h2last[b, :], W_fc[0,:]) + b_fc[0]
// =====================================================================================
__global__ void fc_kernel(const float* __restrict__ h2l, const float* __restrict__ Wfc,
                          const float* __restrict__ bfc, float* __restrict__ out)
{
    __shared__ float red[8];
    int b = blockIdx.x, tid = threadIdx.x;
    float v = h2l[(size_t)b * H_ + tid] * Wfc[tid];
#pragma unroll
    for (int o = 16; o > 0; o >>= 1) v += __shfl_down_sync(0xffffffffu, v, o);
    if ((tid & 31) == 0) red[tid >> 5] = v;
    __syncthreads();
    if (tid < 8) {
        float s = red[tid];
#pragma unroll
        for (int o = 4; o > 0; o >>= 1) s += __shfl_down_sync(0xffu, s, o);
        if (tid == 0) out[b] = s + bfc[0];
    }
}

// =====================================================================================
extern "C" void kernel_launch(void* const* d_in, const int* in_sizes, int n_in,
                              void* d_out, int out_size)
{
    const float* x     = (const float*)d_in[0];
    const float* W_ih0 = (const float*)d_in[1];
    const float* W_hh0 = (const float*)d_in[2];
    const float* b_ih0 = (const float*)d_in[3];
    const float* b_hh0 = (const float*)d_in[4];
    const float* W_ih1 = (const float*)d_in[5];
    const float* W_hh1 = (const float*)d_in[6];
    const float* b_ih1 = (const float*)d_in[7];
    const float* b_hh1 = (const float*)d_in[8];
    const float* W_fc  = (const float*)d_in[9];
    const float* b_fc  = (const float*)d_in[10];
    float* out = (float*)d_out;

    float *xp, *h2l;
    cudaGetSymbolAddress((void**)&xp, g_xp);
    cudaGetSymbolAddress((void**)&h2l, g_h2last);

    dim3 ggemm(M_ / 128, H_ / 128);

    // Phase A: xp0 = x @ W_ih0^T + b_ih0 + b_hh0
    gemm_bias_kernel<<<ggemm, 256>>>(x, W_ih0, b_ih0, b_hh0, xp, IN_);
    // Phase B: fused layer0+layer1 recurrence (pipelined, T+1 steps)
    rnn_fused<<<16 * RANKS, 256>>>(xp, W_hh0, W_ih1, W_hh1, b_ih1, b_hh1, h2l);
    // Phase C: final projection
    fc_kernel<<<B_, H_>>>(h2l, W_fc, b_fc, out);
}

// round 4
// speedup vs baseline: 2.3715x; 2.3715x over previous
#include <cuda_runtime.h>
#include <math.h>

#define B_  64
#define T_  2048
#define IN_ 128
#define H_  256
#define M_  (B_ * T_)

// ---------------- scratch (static device allocations; no cudaMalloc) ----------------
__device__ float g_xp[(size_t)B_ * T_ * H_];    // reused for xp0 then xp1
__device__ float g_h1[(size_t)B_ * T_ * H_];    // layer-0 hidden states
__device__ float g_h2last[(size_t)B_ * H_];     // h2[:, T-1, :]

// ---------------- packed fp32x2 helpers (sm_103a) ----------------
__device__ __forceinline__ void fma2(unsigned long long &d, unsigned long long a, unsigned long long b) {
    asm("fma.rn.f32x2 %0, %1, %2, %0;" : "+l"(d) : "l"(a), "l"(b));
}
__device__ __forceinline__ unsigned long long splat2(float x) {
    unsigned long long r; asm("mov.b64 %0, {%1, %1};" : "=l"(r) : "f"(x)); return r;
}
__device__ __forceinline__ float lo2(unsigned long long v) { return __uint_as_float((unsigned)(v & 0xffffffffULL)); }
__device__ __forceinline__ float hi2(unsigned long long v) { return __uint_as_float((unsigned)(v >> 32)); }

// ---------------- cluster / mbarrier helpers ----------------
__device__ __forceinline__ unsigned su32(const void* p) {
    return (unsigned)__cvta_generic_to_shared(p);
}
__device__ __forceinline__ unsigned cta_rank() {
    unsigned r; asm("mov.u32 %0, %%cluster_ctarank;" : "=r"(r)); return r;
}
__device__ __forceinline__ unsigned mapa_u32(unsigned addr, unsigned rank) {
    unsigned r; asm("mapa.shared::cluster.u32 %0, %1, %2;" : "=r"(r) : "r"(addr), "r"(rank));
    return r;
}
__device__ __forceinline__ void mbar_init(unsigned addr, unsigned cnt) {
    asm volatile("mbarrier.init.shared.b64 [%0], %1;" :: "r"(addr), "r"(cnt) : "memory");
}
__device__ __forceinline__ void mbar_expect_tx(unsigned addr, unsigned bytes) {
    asm volatile("mbarrier.arrive.expect_tx.shared.b64 _, [%0], %1;" :: "r"(addr), "r"(bytes) : "memory");
}
__device__ __forceinline__ void mbar_wait_cluster(unsigned addr, unsigned parity) {
    asm volatile(
        "{\n\t.reg .pred P;\n\t"
        "WL_%=:\n\t"
        "mbarrier.try_wait.parity.acquire.cluster.shared::cta.b64 P, [%0], %1, 0x989680;\n\t"
        "@P bra.uni WD_%=;\n\t"
        "bra.uni WL_%=;\n\t"
        "WD_%=:\n\t}"
        :: "r"(addr), "r"(parity) : "memory");
}
__device__ __forceinline__ void st_async_f32(unsigned remote_addr, float v, unsigned remote_mbar) {
    asm volatile(
        "st.async.shared::cluster.mbarrier::complete_tx::bytes.b32 [%0], %1, [%2];"
        :: "r"(remote_addr), "r"(__float_as_uint(v)), "r"(remote_mbar) : "memory");
}
__device__ __forceinline__ void cluster_sync_() {
    asm volatile("barrier.cluster.arrive.aligned;" ::: "memory");
    asm volatile("barrier.cluster.wait.aligned;" ::: "memory");
}

// =====================================================================================
// Phase A / C: C[m][n] = sum_k A[m][k] * W[n][k] + bias0[n] + bias1[n]
// =====================================================================================
__global__ __launch_bounds__(256, 2)
void gemm_bias_kernel(const float* __restrict__ A, const float* __restrict__ W,
                      const float* __restrict__ bias0, const float* __restrict__ bias1,
                      float* __restrict__ C, int K)
{
    __shared__ float a_sm[16][132];
    __shared__ float b_sm[16][132];

    const int tid = threadIdx.x;
    const int tx = tid & 15, ty = tid >> 4;
    const int mBase = blockIdx.x * 128;
    const int nBase = blockIdx.y * 128;

    unsigned long long acc[8][4];
#pragma unroll
    for (int i = 0; i < 8; i++)
#pragma unroll
        for (int j = 0; j < 4; j++) acc[i][j] = 0ULL;

    for (int kt = 0; kt < K; kt += 16) {
#pragma unroll
        for (int l = 0; l < 2; l++) {
            int idx = l * 256 + tid;
            int row = idx >> 2, kq = idx & 3;
            float4 v = *(const float4*)(A + (size_t)(mBase + row) * K + kt + kq * 4);
            a_sm[kq * 4 + 0][row] = v.x; a_sm[kq * 4 + 1][row] = v.y;
            a_sm[kq * 4 + 2][row] = v.z; a_sm[kq * 4 + 3][row] = v.w;
        }
#pragma unroll
        for (int l = 0; l < 2; l++) {
            int idx = l * 256 + tid;
            int row = idx >> 2, kq = idx & 3;
            float4 v = *(const float4*)(W + (size_t)(nBase + row) * K + kt + kq * 4);
            b_sm[kq * 4 + 0][row] = v.x; b_sm[kq * 4 + 1][row] = v.y;
            b_sm[kq * 4 + 2][row] = v.z; b_sm[kq * 4 + 3][row] = v.w;
        }
        __syncthreads();

#pragma unroll
        for (int kk = 0; kk < 16; kk++) {
            float4 a0 = *(const float4*)&a_sm[kk][ty * 8];
            float4 a1 = *(const float4*)&a_sm[kk][ty * 8 + 4];
            ulonglong2 b0 = *(const ulonglong2*)&b_sm[kk][tx * 8];
            ulonglong2 b1 = *(const ulonglong2*)&b_sm[kk][tx * 8 + 4];
            float av[8] = {a0.x, a0.y, a0.z, a0.w, a1.x, a1.y, a1.z, a1.w};
#pragma unroll
            for (int i = 0; i < 8; i++) {
                unsigned long long s = splat2(av[i]);
                fma2(acc[i][0], s, b0.x);
                fma2(acc[i][1], s, b0.y);
                fma2(acc[i][2], s, b1.x);
                fma2(acc[i][3], s, b1.y);
            }
        }
        __syncthreads();
    }

    const int n0 = nBase + tx * 8;
    float bj[8];
#pragma unroll
    for (int j = 0; j < 8; j++) bj[j] = bias0[n0 + j] + bias1[n0 + j];

#pragma unroll
    for (int i = 0; i < 8; i++) {
        int m = mBase + ty * 8 + i;
        float4 o0, o1;
        o0.x = lo2(acc[i][0]) + bj[0]; o0.y = hi2(acc[i][0]) + bj[1];
        o0.z = lo2(acc[i][1]) + bj[2]; o0.w = hi2(acc[i][1]) + bj[3];
        o1.x = lo2(acc[i][2]) + bj[4]; o1.y = hi2(acc[i][2]) + bj[5];
        o1.z = lo2(acc[i][3]) + bj[6]; o1.w = hi2(acc[i][3]) + bj[7];
        *(float4*)(C + (size_t)m * H_ + n0)     = o0;
        *(float4*)(C + (size_t)m * H_ + n0 + 4) = o1;
    }
}

// =====================================================================================
// Recurrence: 64 clusters x 2 CTAs, 1 batch row per cluster, 256 threads/CTA.
// CTA rank r owns outputs [128r, 128r+128).
// Warp split: warps 0-3 (group 0) compute the OWN k-half (dims this CTA produced
// locally last step -> no mbar needed); warps 4-7 (group 1) wait on the mbar and
// compute the PEER k-half (arrives via st.async). This hides the DSMEM flight
// (~215-275 cyc) under phase-1 compute.
// Twin epilogue: 2 threads/output; twin 0 stores local smem (+global), twin 1
// does the st.async to the peer. Double-buffered h, mbar[t&1], parity (t>>1)&1.
// STORE_ALL=true -> stream all h[t] to hout (layer 0); false -> write only
// h[T-1] to hout laid out [b][H] (layer 1).
// =====================================================================================
template<bool STORE_ALL>
__global__ void __cluster_dims__(2, 1, 1) __launch_bounds__(256, 1)
rnn_rec2(const float* __restrict__ xp, const float* __restrict__ Whh,
         float* __restrict__ hout)
{
    __shared__ __align__(16) float h_sm[2][256];
    __shared__ __align__(16) float p_sm[2][128];
    __shared__ __align__(8)  unsigned long long mbar[2];

    const int tid = threadIdx.x;
    const unsigned rank = cta_rank();              // 0 or 1
    const unsigned peer = rank ^ 1u;
    const int b = blockIdx.x >> 1;                 // batch row
    const int w = tid >> 5, l = tid & 31;
    const int grp = w >> 2;                        // 0: own-half warps, 1: peer-half warps
    const int kh  = grp ? (int)peer : (int)rank;   // which k-half this thread covers
    const int o   = (w & 3) * 32 + l;              // local output 0..127
    const int rbase = (int)rank * 128;

    // ---- W slice into registers: W[rbase+o][kh*128 .. +128) as 32 ulonglong2 ----
    unsigned long long wq[64];
    {
        const ulonglong2* src = (const ulonglong2*)(Whh + (size_t)(rbase + o) * H_ + kh * 128);
#pragma unroll
        for (int j = 0; j < 32; ++j) { ulonglong2 v = src[j]; wq[2 * j] = v.x; wq[2 * j + 1] = v.y; }
    }

    // ---- init ----
    if (tid == 0) { mbar_init(su32(&mbar[0]), 1); mbar_init(su32(&mbar[1]), 1); }
    for (int i = tid; i < 512; i += 256) ((float*)h_sm)[i] = 0.f;   // h[-1] = 0 (both bufs)
    __syncthreads();
    cluster_sync_();                                                 // peer mbars live

    const unsigned my_mbar  = su32(&mbar[0]);
    const unsigned peer_mbar = mapa_u32(my_mbar, peer);
    const unsigned peer_h0   = mapa_u32(su32(&h_sm[0][0]), peer);

    // epilogue mapping: twin d, output oe
    const int d  = tid >> 7;          // 0: local store (+global), 1: st.async
    const int oe = tid & 127;
    const size_t xrow = ((size_t)b * T_) * H_ + rbase + oe;

    float xv = __ldg(xp + xrow);      // xp[b][0][rbase+oe] (both twins load; broadcast)

    for (int t = 0; t < T_; ++t) {
        const int cb = t & 1, nb = cb ^ 1;

        // prefetch xp for t+1 (latency hidden under wait + compute)
        float xvn = 0.f;
        if (t + 1 < T_) xvn = __ldg(xp + xrow + (size_t)(t + 1) * H_);

        if (tid == 0) mbar_expect_tx(my_mbar + (unsigned)cb * 8u, 512u);
        if (grp == 1 && t > 0)
            mbar_wait_cluster(my_mbar + (unsigned)((t - 1) & 1) * 8u,
                              (unsigned)((t - 1) >> 1) & 1u);

        // ---- matvec: 128-k partial for output o over half kh, 4 accumulators ----
        const float* hb = &h_sm[cb][kh * 128];
        unsigned long long a0 = 0, a1 = 0, a2 = 0, a3 = 0;
#pragma unroll
        for (int kk = 0; kk < 32; kk += 2) {
            ulonglong2 v0 = *(const ulonglong2*)(hb + kk * 4);       // broadcast LDS.128
            ulonglong2 v1 = *(const ulonglong2*)(hb + kk * 4 + 4);
            fma2(a0, v0.x, wq[2 * kk]);
            fma2(a1, v0.y, wq[2 * kk + 1]);
            fma2(a2, v1.x, wq[2 * kk + 2]);
            fma2(a3, v1.y, wq[2 * kk + 3]);
        }
        p_sm[grp][o] = lo2(a0) + hi2(a0) + lo2(a1) + hi2(a1)
                     + lo2(a2) + hi2(a2) + lo2(a3) + hi2(a3);
        __syncthreads();

        // ---- twin epilogue ----
        {
            float s = xv + p_sm[0][oe] + p_sm[1][oe];
            float h = tanhf(s);
            if (d == 0) {
                h_sm[nb][rbase + oe] = h;                             // own copy for t+1
                if (STORE_ALL)
                    hout[((size_t)b * T_ + t) * H_ + rbase + oe] = h;
                else if (t == T_ - 1)
                    hout[(size_t)b * H_ + rbase + oe] = h;
            } else {
                st_async_f32(peer_h0 + (unsigned)(nb * 256 + rbase + oe) * 4u,
                             h, peer_mbar + (unsigned)cb * 8u);       // peer copy + tx
            }
        }
        __syncthreads();
        xv = xvn;
    }

    // drain: final incoming st.async batch must land before any CTA exits
    mbar_wait_cluster(my_mbar + (unsigned)((T_ - 1) & 1) * 8u,
                      (unsigned)((T_ - 1) >> 1) & 1u);
    cluster_sync_();
}

// =====================================================================================
// Final FC: out[b] = dot(h2last[b, :], W_fc[0,:]) + b_fc[0]
// =====================================================================================
__global__ void fc_kernel(const float* __restrict__ h2l, const float* __restrict__ Wfc,
                          const float* __restrict__ bfc, float* __restrict__ out)
{
    __shared__ float red[8];
    int b = blockIdx.x, tid = threadIdx.x;
    float v = h2l[(size_t)b * H_ + tid] * Wfc[tid];
#pragma unroll
    for (int o = 16; o > 0; o >>= 1) v += __shfl_down_sync(0xffffffffu, v, o);
    if ((tid & 31) == 0) red[tid >> 5] = v;
    __syncthreads();
    if (tid < 8) {
        float s = red[tid];
#pragma unroll
        for (int o = 4; o > 0; o >>= 1) s += __shfl_down_sync(0xffu, s, o);
        if (tid == 0) out[b] = s + bfc[0];
    }
}

// =====================================================================================
extern "C" void kernel_launch(void* const* d_in, const int* in_sizes, int n_in,
                              void* d_out, int out_size)
{
    const float* x     = (const float*)d_in[0];
    const float* W_ih0 = (const float*)d_in[1];
    const float* W_hh0 = (const float*)d_in[2];
    const float* b_ih0 = (const float*)d_in[3];
    const float* b_hh0 = (const float*)d_in[4];
    const float* W_ih1 = (const float*)d_in[5];
    const float* W_hh1 = (const float*)d_in[6];
    const float* b_ih1 = (const float*)d_in[7];
    const float* b_hh1 = (const float*)d_in[8];
    const float* W_fc  = (const float*)d_in[9];
    const float* b_fc  = (const float*)d_in[10];
    float* out = (float*)d_out;

    float *xp, *h1, *h2l;
    cudaGetSymbolAddress((void**)&xp, g_xp);
    cudaGetSymbolAddress((void**)&h1, g_h1);
    cudaGetSymbolAddress((void**)&h2l, g_h2last);

    dim3 ggemm(M_ / 128, H_ / 128);

    // Phase A: xp0 = x @ W_ih0^T + b_ih0 + b_hh0
    gemm_bias_kernel<<<ggemm, 256>>>(x, W_ih0, b_ih0, b_hh0, xp, IN_);
    // Phase B: layer-0 recurrence -> h1 (streams all steps)
    rnn_rec2<true><<<128, 256>>>(xp, W_hh0, h1);
    // Phase C: xp1 = h1 @ W_ih1^T + b_ih1 + b_hh1
    gemm_bias_kernel<<<ggemm, 256>>>(h1, W_ih1, b_ih1, b_hh1, xp, H_);
    // Phase D: layer-1 recurrence -> only h2[T-1]
    rnn_rec2<false><<<128, 256>>>(xp, W_hh1, h2l);
    // Phase E: final projection
    fc_kernel<<<B_, H_>>>(h2l, W_fc, b_fc, out);
}

// round 5
// speedup vs baseline: 2.4749x; 1.0436x over previous
#include <cuda_runtime.h>
#include <math.h>

#define B_  64
#define T_  2048
#define IN_ 128
#define H_  256
#define M_  (B_ * T_)

// ---------------- scratch (static device allocations; no cudaMalloc) ----------------
__device__ float g_xp[(size_t)B_ * T_ * H_];    // reused for xp0 then xp1
__device__ float g_h1[(size_t)B_ * T_ * H_];    // layer-0 hidden states
__device__ float g_h2last[(size_t)B_ * H_];     // h2[:, T-1, :]

// ---------------- packed fp32x2 helpers (sm_103a) ----------------
__device__ __forceinline__ void fma2(unsigned long long &d, unsigned long long a, unsigned long long b) {
    asm("fma.rn.f32x2 %0, %1, %2, %0;" : "+l"(d) : "l"(a), "l"(b));
}
__device__ __forceinline__ unsigned long long splat2(float x) {
    unsigned long long r; asm("mov.b64 %0, {%1, %1};" : "=l"(r) : "f"(x)); return r;
}
__device__ __forceinline__ float lo2(unsigned long long v) { return __uint_as_float((unsigned)(v & 0xffffffffULL)); }
__device__ __forceinline__ float hi2(unsigned long long v) { return __uint_as_float((unsigned)(v >> 32)); }

// fast tanh: 1 - 2/(exp(2x)+1) via MUFU ex2/rcp; abs err ~5e-7, monotone, saturates
__device__ __forceinline__ float tanh_fast(float s) {
    s = fminf(fmaxf(s, -15.f), 15.f);
    float e;
    asm("ex2.approx.f32 %0, %1;" : "=f"(e) : "f"(s * 2.885390082f));  // e = 2^(2x*log2e) = e^(2x)
    float r;
    asm("rcp.approx.f32 %0, %1;" : "=f"(r) : "f"(e + 1.f));
    return fmaf(-2.f, r, 1.f);
}

// ---------------- cluster / mbarrier helpers ----------------
__device__ __forceinline__ unsigned su32(const void* p) {
    return (unsigned)__cvta_generic_to_shared(p);
}
__device__ __forceinline__ unsigned cta_rank() {
    unsigned r; asm("mov.u32 %0, %%cluster_ctarank;" : "=r"(r)); return r;
}
__device__ __forceinline__ unsigned mapa_u32(unsigned addr, unsigned rank) {
    unsigned r; asm("mapa.shared::cluster.u32 %0, %1, %2;" : "=r"(r) : "r"(addr), "r"(rank));
    return r;
}
__device__ __forceinline__ void mbar_init(unsigned addr, unsigned cnt) {
    asm volatile("mbarrier.init.shared.b64 [%0], %1;" :: "r"(addr), "r"(cnt) : "memory");
}
__device__ __forceinline__ void mbar_expect_tx(unsigned addr, unsigned bytes) {
    asm volatile("mbarrier.arrive.expect_tx.shared.b64 _, [%0], %1;" :: "r"(addr), "r"(bytes) : "memory");
}
__device__ __forceinline__ void mbar_wait_cluster(unsigned addr, unsigned parity) {
    asm volatile(
        "{\n\t.reg .pred P;\n\t"
        "WL_%=:\n\t"
        "mbarrier.try_wait.parity.acquire.cluster.shared::cta.b64 P, [%0], %1, 0x989680;\n\t"
        "@P bra.uni WD_%=;\n\t"
        "bra.uni WL_%=;\n\t"
        "WD_%=:\n\t}"
        :: "r"(addr), "r"(parity) : "memory");
}
__device__ __forceinline__ void st_async_f32(unsigned remote_addr, float v, unsigned remote_mbar) {
    asm volatile(
        "st.async.shared::cluster.mbarrier::complete_tx::bytes.b32 [%0], %1, [%2];"
        :: "r"(remote_addr), "r"(__float_as_uint(v)), "r"(remote_mbar) : "memory");
}
__device__ __forceinline__ void cluster_sync_() {
    asm volatile("barrier.cluster.arrive.aligned;" ::: "memory");
    asm volatile("barrier.cluster.wait.aligned;" ::: "memory");
}

// =====================================================================================
// Phase A / C: C[m][n] = sum_k A[m][k] * W[n][k] + bias0[n] + bias1[n]
// =====================================================================================
__global__ __launch_bounds__(256, 2)
void gemm_bias_kernel(const float* __restrict__ A, const float* __restrict__ W,
                      const float* __restrict__ bias0, const float* __restrict__ bias1,
                      float* __restrict__ C, int K)
{
    __shared__ float a_sm[16][132];
    __shared__ float b_sm[16][132];

    const int tid = threadIdx.x;
    const int tx = tid & 15, ty = tid >> 4;
    const int mBase = blockIdx.x * 128;
    const int nBase = blockIdx.y * 128;

    unsigned long long acc[8][4];
#pragma unroll
    for (int i = 0; i < 8; i++)
#pragma unroll
        for (int j = 0; j < 4; j++) acc[i][j] = 0ULL;

    for (int kt = 0; kt < K; kt += 16) {
#pragma unroll
        for (int l = 0; l < 2; l++) {
            int idx = l * 256 + tid;
            int row = idx >> 2, kq = idx & 3;
            float4 v = *(const float4*)(A + (size_t)(mBase + row) * K + kt + kq * 4);
            a_sm[kq * 4 + 0][row] = v.x; a_sm[kq * 4 + 1][row] = v.y;
            a_sm[kq * 4 + 2][row] = v.z; a_sm[kq * 4 + 3][row] = v.w;
        }
#pragma unroll
        for (int l = 0; l < 2; l++) {
            int idx = l * 256 + tid;
            int row = idx >> 2, kq = idx & 3;
            float4 v = *(const float4*)(W + (size_t)(nBase + row) * K + kt + kq * 4);
            b_sm[kq * 4 + 0][row] = v.x; b_sm[kq * 4 + 1][row] = v.y;
            b_sm[kq * 4 + 2][row] = v.z; b_sm[kq * 4 + 3][row] = v.w;
        }
        __syncthreads();

#pragma unroll
        for (int kk = 0; kk < 16; kk++) {
            float4 a0 = *(const float4*)&a_sm[kk][ty * 8];
            float4 a1 = *(const float4*)&a_sm[kk][ty * 8 + 4];
            ulonglong2 b0 = *(const ulonglong2*)&b_sm[kk][tx * 8];
            ulonglong2 b1 = *(const ulonglong2*)&b_sm[kk][tx * 8 + 4];
            float av[8] = {a0.x, a0.y, a0.z, a0.w, a1.x, a1.y, a1.z, a1.w};
#pragma unroll
            for (int i = 0; i < 8; i++) {
                unsigned long long s = splat2(av[i]);
                fma2(acc[i][0], s, b0.x);
                fma2(acc[i][1], s, b0.y);
                fma2(acc[i][2], s, b1.x);
                fma2(acc[i][3], s, b1.y);
            }
        }
        __syncthreads();
    }

    const int n0 = nBase + tx * 8;
    float bj[8];
#pragma unroll
    for (int j = 0; j < 8; j++) bj[j] = bias0[n0 + j] + bias1[n0 + j];

#pragma unroll
    for (int i = 0; i < 8; i++) {
        int m = mBase + ty * 8 + i;
        float4 o0, o1;
        o0.x = lo2(acc[i][0]) + bj[0]; o0.y = hi2(acc[i][0]) + bj[1];
        o0.z = lo2(acc[i][1]) + bj[2]; o0.w = hi2(acc[i][1]) + bj[3];
        o1.x = lo2(acc[i][2]) + bj[4]; o1.y = hi2(acc[i][2]) + bj[5];
        o1.z = lo2(acc[i][3]) + bj[6]; o1.w = hi2(acc[i][3]) + bj[7];
        *(float4*)(C + (size_t)m * H_ + n0)     = o0;
        *(float4*)(C + (size_t)m * H_ + n0 + 4) = o1;
    }
}

// =====================================================================================
// Recurrence v3: 64 clusters x 2 CTAs, 1 batch row per cluster, 256 threads/CTA.
// CTA rank r owns outputs [128r, 128r+128).
// Lane-pair decomposition: lanes (2i, 2i+1) of warp w own output o = w*16+i.
// Even lane accumulates the OWN k-half (dims this CTA produced; smem offset 0),
// odd lane the PEER k-half (arrives via st.async; smem offset 132 -> bank-disjoint).
// Combine with one shfl.down(1): no p_sm reduction, ONE __syncthreads per step.
// h buffers: h_sm[buf][264] = [0,128) own outputs | [132,260) peer outputs.
// Protocol identical to round-2 (proven): double buffer, mbar[t&1], parity (t>>1)&1,
// expect_tx 512B per phase, drain before exit.
// =====================================================================================
template<bool STORE_ALL>
__global__ void __cluster_dims__(2, 1, 1) __launch_bounds__(256, 1)
rnn_rec3(const float* __restrict__ xp, const float* __restrict__ Whh,
         float* __restrict__ hout)
{
    __shared__ __align__(16) float h_sm[2][264];
    __shared__ __align__(8)  unsigned long long mbar[2];

    const int tid = threadIdx.x;
    const unsigned rank = cta_rank();              // 0 or 1
    const unsigned peer = rank ^ 1u;
    const int b = blockIdx.x >> 1;                 // batch row
    const int w = tid >> 5, l = tid & 31;
    const int half = l & 1;                        // 0: own k-half, 1: peer k-half
    const int o = w * 16 + (l >> 1);               // local output 0..127
    const int o_glob = (int)rank * 128 + o;
    const int kh = half ? (int)peer : (int)rank;   // k-range of this lane's W slice

    // ---- W slice into registers: W[o_glob][kh*128 .. +128) as 32 ulonglong2 ----
    unsigned long long wq[64];
    {
        const ulonglong2* src = (const ulonglong2*)(Whh + (size_t)o_glob * H_ + kh * 128);
#pragma unroll
        for (int j = 0; j < 32; ++j) { ulonglong2 v = src[j]; wq[2 * j] = v.x; wq[2 * j + 1] = v.y; }
    }

    // ---- init ----
    if (tid == 0) { mbar_init(su32(&mbar[0]), 1); mbar_init(su32(&mbar[1]), 1); }
    for (int i = tid; i < 2 * 264; i += 256) ((float*)h_sm)[i] = 0.f;   // h[-1] = 0
    __syncthreads();
    cluster_sync_();                                // peer mbars live

    const unsigned my_mbar   = su32(&mbar[0]);
    const unsigned peer_mbar = mapa_u32(my_mbar, peer);
    const unsigned peer_h0   = mapa_u32(su32(&h_sm[0][0]), peer);

    // per-lane h base offset within a buffer (floats): own half at 0, peer at 132
    const int hoff = half ? 132 : 0;

    const size_t xrow = ((size_t)b * T_) * H_ + o_glob;
    float xv = (half == 0) ? __ldg(xp + xrow) : 0.f;     // xp[b][0][o_glob]

    for (int t = 0; t < T_; ++t) {
        const int cb = t & 1, nb = cb ^ 1;

        // prefetch xp for t+1 (LDG latency hidden under wait + matvec)
        float xvn = 0.f;
        if (half == 0 && t + 1 < T_) xvn = __ldg(xp + xrow + (size_t)(t + 1) * H_);

        if (t > 0)
            mbar_wait_cluster(my_mbar + (unsigned)nb * 8u,          // nb == (t-1)&1
                              (unsigned)((t - 1) >> 1) & 1u);
        if (tid == 0) mbar_expect_tx(my_mbar + (unsigned)cb * 8u, 512u);

        // ---- matvec: 128-k partial for output o over this lane's half ----
        const float* hb = &h_sm[cb][hoff];
        unsigned long long a0 = 0, a1 = 0, a2 = 0, a3 = 0;
#pragma unroll
        for (int kk = 0; kk < 32; kk += 2) {
            ulonglong2 v0 = *(const ulonglong2*)(hb + kk * 4);       // broadcast LDS.128
            ulonglong2 v1 = *(const ulonglong2*)(hb + kk * 4 + 4);
            fma2(a0, v0.x, wq[2 * kk]);
            fma2(a1, v0.y, wq[2 * kk + 1]);
            fma2(a2, v1.x, wq[2 * kk + 2]);
            fma2(a3, v1.y, wq[2 * kk + 3]);
        }
        float p = lo2(a0) + hi2(a0) + lo2(a1) + hi2(a1)
                + lo2(a2) + hi2(a2) + lo2(a3) + hi2(a3);
        float q = __shfl_down_sync(0xffffffffu, p, 1);               // odd lane's partial

        if (half == 0) {
            float h = tanh_fast(xv + p + q);
            h_sm[nb][o] = h;                                          // own copy for t+1
            st_async_f32(peer_h0 + (unsigned)(nb * 264 + 132 + o) * 4u,
                         h, peer_mbar + (unsigned)cb * 8u);           // peer copy + tx
            if (STORE_ALL)
                hout[((size_t)b * T_ + t) * H_ + o_glob] = h;
            else if (t == T_ - 1)
                hout[(size_t)b * H_ + o_glob] = h;
        }
        __syncthreads();
        xv = xvn;
    }

    // drain: final incoming st.async batch must land before any CTA exits
    mbar_wait_cluster(my_mbar + (unsigned)((T_ - 1) & 1) * 8u,
                      (unsigned)((T_ - 1) >> 1) & 1u);
    cluster_sync_();
}

// =====================================================================================
// Final FC: out[b] = dot(h2last[b, :], W_fc[0,:]) + b_fc[0]
// =====================================================================================
__global__ void fc_kernel(const float* __restrict__ h2l, const float* __restrict__ Wfc,
                          const float* __restrict__ bfc, float* __restrict__ out)
{
    __shared__ float red[8];
    int b = blockIdx.x, tid = threadIdx.x;
    float v = h2l[(size_t)b * H_ + tid] * Wfc[tid];
#pragma unroll
    for (int o = 16; o > 0; o >>= 1) v += __shfl_down_sync(0xffffffffu, v, o);
    if ((tid & 31) == 0) red[tid >> 5] = v;
    __syncthreads();
    if (tid < 8) {
        float s = red[tid];
#pragma unroll
        for (int o = 4; o > 0; o >>= 1) s += __shfl_down_sync(0xffu, s, o);
        if (tid == 0) out[b] = s + bfc[0];
    }
}

// =====================================================================================
extern "C" void kernel_launch(void* const* d_in, const int* in_sizes, int n_in,
                              void* d_out, int out_size)
{
    const float* x     = (const float*)d_in[0];
    const float* W_ih0 = (const float*)d_in[1];
    const float* W_hh0 = (const float*)d_in[2];
    const float* b_ih0 = (const float*)d_in[3];
    const float* b_hh0 = (const float*)d_in[4];
    const float* W_ih1 = (const float*)d_in[5];
    const float* W_hh1 = (const float*)d_in[6];
    const float* b_ih1 = (const float*)d_in[7];
    const float* b_hh1 = (const float*)d_in[8];
    const float* W_fc  = (const float*)d_in[9];
    const float* b_fc  = (const float*)d_in[10];
    float* out = (float*)d_out;

    float *xp, *h1, *h2l;
    cudaGetSymbolAddress((void**)&xp, g_xp);
    cudaGetSymbolAddress((void**)&h1, g_h1);
    cudaGetSymbolAddress((void**)&h2l, g_h2last);

    dim3 ggemm(M_ / 128, H_ / 128);

    // Phase A: xp0 = x @ W_ih0^T + b_ih0 + b_hh0
    gemm_bias_kernel<<<ggemm, 256>>>(x, W_ih0, b_ih0, b_hh0, xp, IN_);
    // Phase B: layer-0 recurrence -> h1 (streams all steps)
    rnn_rec3<true><<<128, 256>>>(xp, W_hh0, h1);
    // Phase C: xp1 = h1 @ W_ih1^T + b_ih1 + b_hh1
    gemm_bias_kernel<<<ggemm, 256>>>(h1, W_ih1, b_ih1, b_hh1, xp, H_);
    // Phase D: layer-1 recurrence -> only h2[T-1]
    rnn_rec3<false><<<128, 256>>>(xp, W_hh1, h2l);
    // Phase E: final projection
    fc_kernel<<<B_, H_>>>(h2l, W_fc, b_fc, out);
}